// round 14
// baseline (speedup 1.0000x reference)
#include <cuda_runtime.h>

#define S 64
#define MAXT 262144
#define L 512
#define NCMAX ((MAXT + L - 1) / L)

// ---- scratch (__device__ globals: no allocation allowed) ----
__device__ float g_e_buf[(size_t)(MAXT + 8) * S];              // e_t rows (+pad rows)
__device__ int g_rollpad[MAXT + 96];                           // roll[t]*64 (prescaled), padded
__device__ unsigned char g_walk[(size_t)NCMAX * S * L];        // per-chunk walks (16 MB)
__device__ int g_boundary[NCMAX + 2];
__device__ int g_final_state;
__device__ float g_final_score;

__device__ __forceinline__ float fmax3(float a, float b, float c) {
    return fmaxf(fmaxf(a, b), c);
}

// =====================================================================
// Kernel 0a: prescaled padded roll offsets (roll*64 = row offset in table)
// =====================================================================
__global__ void prep_kernel(const int* __restrict__ rolls, int T)
{
    int i = blockIdx.x * blockDim.x + threadIdx.x;
    if (i < T + 96) g_rollpad[i] = rolls[(i < T) ? i : (T - 1)] * 64;
}

// Kernel 0b: no-op launch-index shims (keep ncu -s 5 landing on fwd_kernel)
__global__ void dummy_kernel() {}

// =====================================================================
// Kernel 1: serial Viterbi forward (values only). 128 threads, 4 warps.
// Thread pair per state j. 12-step unroll, dual 6-reg ll banks.
// R11 base + minimal 16-op FMNMX3 tree + prescaled roll offsets.
// =====================================================================
__global__ __launch_bounds__(128, 1)
void fwd_kernel(const int* __restrict__ rolls,
                const float* __restrict__ trans,
                const float* __restrict__ table, int T)
{
    // padded e layout: i<32 at [i], i>=32 at [36+i-32] -> bank-disjoint halves
    __shared__ __align__(16) float smem_e[2][68];
    __shared__ float smem_d[S];

    const int tid = threadIdx.x;
    const int w = tid >> 5, l = tid & 31;
    const int j = w * 16 + (l >> 1);
    const int half = l & 1;
    const int ibase = half << 5;
    const bool lead = (half == 0);
    const int pos = (j < 32) ? j : (36 + (j - 32));
    const int ebOff = half ? 36 : 0;

    float TR[32];
#pragma unroll
    for (int k = 0; k < 32; k++) TR[k] = trans[j * 65 + ibase + k];

    // ---- init: delta_0 = trans[:,64] + ll_0 ; e_1 = ll_1 + delta_0 ----
    {
        int r0 = rolls[0];
        int r1 = rolls[(T > 1) ? 1 : 0];
        float ll0 = table[r0 * S + j];
        float d0 = trans[j * 65 + 64] + ll0;
        if (T == 1 && lead) smem_d[j] = d0;
        float e1 = table[r1 * S + j] + d0;
        if (lead) smem_e[1][pos] = e1;
        else      g_e_buf[j] = e1;
    }
    // bank A: ll for steps t..t+5 (t=1 -> ll_2..ll_7); bank B refilled in-flight
    float llA0 = table[g_rollpad[2] + j];
    float llA1 = table[g_rollpad[3] + j];
    float llA2 = table[g_rollpad[4] + j];
    float llA3 = table[g_rollpad[5] + j];
    float llA4 = table[g_rollpad[6] + j];
    float llA5 = table[g_rollpad[7] + j];
    float llB0, llB1, llB2, llB3, llB4, llB5;

    const int* rp = g_rollpad + 8;                  // roll off_{t+7} at t=1
    float* epp = g_e_buf + (size_t)S + j;           // e-store row for t=1
    __syncthreads();

    float delta = 0.0f;

    // One step: STATIC parity RP/WP, static store offset OFF (0..11),
    // consume LLSRC (ll_{t+OFF+1}), refill LLDST with ll_{t+OFF+7}.
    // Candidates via FFMA-imm (E*1.0+TR bit-exact, rt=1).
    // Minimal 16-op selection tree (FMNMX3-shaped, quad-major, bit-exact).
#define VSTEP(RP, WP, OFF, LLSRC, LLDST)                                       \
    {                                                                          \
        int rn64 = rp[OFF];                                                    \
        LLDST = table[rn64 + j];                                               \
        float u[8], wv[8];                                                     \
        {                                                                      \
            const float4* eb =                                                 \
                reinterpret_cast<const float4*>(&smem_e[RP][ebOff]);           \
            _Pragma("unroll")                                                  \
            for (int q = 0; q < 8; q++) {                                      \
                float4 f = eb[q];                                              \
                float a = __fmaf_rn(f.x, 1.0f, TR[4*q]);                       \
                float b = __fmaf_rn(f.y, 1.0f, TR[4*q+1]);                     \
                float c = __fmaf_rn(f.z, 1.0f, TR[4*q+2]);                     \
                float d = __fmaf_rn(f.w, 1.0f, TR[4*q+3]);                     \
                u[q]  = fmax3(a, b, c);                                        \
                wv[q] = d;                                                     \
            }                                                                  \
        }                                                                      \
        float v0 = fmax3(u[0], u[1], u[2]);                                    \
        float v1 = fmax3(u[3], u[4], u[5]);                                    \
        float v2 = fmax3(u[6], u[7], wv[0]);                                   \
        float v3 = fmax3(wv[1], wv[2], wv[3]);                                 \
        float v4 = fmax3(wv[4], wv[5], wv[6]);                                 \
        float z0 = fmax3(v0, v1, v2);                                          \
        float z1 = fmax3(v3, v4, wv[7]);                                       \
        float m  = fmaxf(z0, z1);                                              \
        float mo = __shfl_xor_sync(0xffffffffu, m, 1);                         \
        delta = fmaxf(m, mo);                                                  \
        float ep = LLSRC + delta;        /* e_{t+1} = ll_{t+1} + delta_t */    \
        if (lead) smem_e[WP][pos] = ep;                                        \
        else      epp[(OFF) * S] = ep;                                         \
        __syncthreads();                                                       \
    }

    int t = 1;
    // main loop: 12 steps/iter; t stays odd; parities (1,0),(0,1) repeating
    for (; t + 11 < T; t += 12) {
        VSTEP(1, 0, 0,  llA0, llB0);
        VSTEP(0, 1, 1,  llA1, llB1);
        VSTEP(1, 0, 2,  llA2, llB2);
        VSTEP(0, 1, 3,  llA3, llB3);
        VSTEP(1, 0, 4,  llA4, llB4);
        VSTEP(0, 1, 5,  llA5, llB5);
        VSTEP(1, 0, 6,  llB0, llA0);
        VSTEP(0, 1, 7,  llB1, llA1);
        VSTEP(1, 0, 8,  llB2, llA2);
        VSTEP(0, 1, 9,  llB3, llA3);
        VSTEP(1, 0, 10, llB4, llA4);
        VSTEP(0, 1, 11, llB5, llA5);
        rp += 12;
        epp += 12 * S;
    }
#undef VSTEP

    // tail (<=11 steps): runtime parity, direct ll loads (stalls irrelevant)
    for (; t < T; t++) {
        const int rpar = t & 1, wpar = (t + 1) & 1;
        float u[8], wv[8];
        {
            const float4* eb = reinterpret_cast<const float4*>(&smem_e[rpar][ebOff]);
#pragma unroll
            for (int q = 0; q < 8; q++) {
                float4 f = eb[q];
                float a = __fmaf_rn(f.x, 1.0f, TR[4*q]);
                float b = __fmaf_rn(f.y, 1.0f, TR[4*q+1]);
                float c = __fmaf_rn(f.z, 1.0f, TR[4*q+2]);
                float d = __fmaf_rn(f.w, 1.0f, TR[4*q+3]);
                u[q]  = fmax3(a, b, c);
                wv[q] = d;
            }
        }
        float v0 = fmax3(u[0], u[1], u[2]);
        float v1 = fmax3(u[3], u[4], u[5]);
        float v2 = fmax3(u[6], u[7], wv[0]);
        float v3 = fmax3(wv[1], wv[2], wv[3]);
        float v4 = fmax3(wv[4], wv[5], wv[6]);
        float z0 = fmax3(v0, v1, v2);
        float z1 = fmax3(v3, v4, wv[7]);
        float m  = fmaxf(z0, z1);
        float mo = __shfl_xor_sync(0xffffffffu, m, 1);
        delta = fmaxf(m, mo);
        float ep = table[g_rollpad[t + 1] + j] + delta;
        if (lead) smem_e[wpar][pos] = ep;
        else      g_e_buf[(size_t)t * S + j] = ep;
        __syncthreads();
    }

    if (T > 1 && lead) smem_d[j] = delta;
    __syncthreads();
    if (tid == 0) {
        float best = smem_d[0]; int bi = 0;
        for (int q = 1; q < S; q++) {           // first-argmax (strict >)
            float vq = smem_d[q];
            if (vq > best) { best = vq; bi = q; }
        }
        g_final_state = bi;
        g_final_score = best;
    }
}

// =====================================================================
// Kernel 2: per-chunk backpointer recompute (bit-identical candidates,
// first-argmax via ascending strict >) + all-64-endstate backtrack walks.
// =====================================================================
__global__ __launch_bounds__(512, 1)
void bp_chunk_kernel(const float* __restrict__ trans, int T)
{
    __shared__ signed char bp_s[L * S];                 // 32 KB
    __shared__ __align__(16) float se[8][S];
    const int c = blockIdx.x;
    const int tid = threadIdx.x;
    const int tg = tid >> 6;
    const int j = tid & 63;
    int nr = (T - 1) - c * L; if (nr > L) nr = L; if (nr < 0) nr = 0;

    float TRv[64];
#pragma unroll
    for (int i = 0; i < 64; i++) TRv[i] = trans[j * 65 + i];

    for (int k = 0; k < L / 8; k++) {
        const int r = k * 8 + tg;
        const bool act = r < nr;
        if (act) se[tg][j] = g_e_buf[((size_t)(c * L + r)) * S + j];
        __syncthreads();
        if (act) {
            const float4* ep = reinterpret_cast<const float4*>(se[tg]);
            float4 e0 = ep[0];
            float m = TRv[0] + e0.x; int a = 0;
            float cc = TRv[1] + e0.y; if (cc > m) { m = cc; a = 1; }
            cc = TRv[2] + e0.z; if (cc > m) { m = cc; a = 2; }
            cc = TRv[3] + e0.w; if (cc > m) { m = cc; a = 3; }
#pragma unroll
            for (int q = 1; q < 16; q++) {
                float4 ev = ep[q];
                cc = TRv[4*q]   + ev.x; if (cc > m) { m = cc; a = 4*q;   }
                cc = TRv[4*q+1] + ev.y; if (cc > m) { m = cc; a = 4*q+1; }
                cc = TRv[4*q+2] + ev.z; if (cc > m) { m = cc; a = 4*q+2; }
                cc = TRv[4*q+3] + ev.w; if (cc > m) { m = cc; a = 4*q+3; }
            }
            bp_s[r * S + j] = (signed char)a;
        }
        __syncthreads();
    }

    if (tid < S) {
        int s = tid;
        const size_t wb = ((size_t)c * S + tid) * L;
        if (nr < L) g_walk[wb + nr] = (unsigned char)s;
        for (int r = nr - 1; r >= 0; r--) {
            s = bp_s[r * S + s];
            g_walk[wb + r] = (unsigned char)s;
        }
    }
}

// =====================================================================
// Kernel 3: serial chunk-map composition -> per-chunk boundary states
// =====================================================================
__global__ void compose_kernel(int T)
{
    __shared__ unsigned char mp[L * S];
    int nc = (T >= 2) ? ((T - 2) / L + 1) : 1;
    for (int q = threadIdx.x; q < nc * S; q += blockDim.x)
        mp[q] = g_walk[(size_t)q * L];
    __syncthreads();
    if (threadIdx.x == 0) {
        int s = g_final_state;
        g_boundary[nc] = s;
        for (int c = nc - 1; c >= 0; c--) {
            s = mp[c * S + s];
            g_boundary[c] = s;
        }
    }
}

// =====================================================================
// Kernel 4: parallel path fill, reverse-time order: out[T-1-t] = s_t
// =====================================================================
__global__ void fill_kernel(float* __restrict__ out, int T, int out_size)
{
    const int c = blockIdx.x;
    const int m = threadIdx.x;
    const int t = c * L + m;
    if (t < T) {
        const int sel = g_boundary[c + 1];
        unsigned char s = g_walk[((size_t)c * S + sel) * L + m];
        const int oi = T - 1 - t;
        if (oi >= 0 && oi < out_size) out[oi] = (float)s;
    }
    if (c == 0 && m == 0 && T < out_size) out[T] = g_final_score;
}

// =====================================================================
extern "C" void kernel_launch(void* const* d_in, const int* in_sizes, int n_in,
                              void* d_out, int out_size)
{
    const int* rolls = nullptr;
    const float* trans = nullptr;
    const float* table = nullptr;
    int T = 0;
    for (int i = 0; i < n_in; i++) {
        const int sz = in_sizes[i];
        if (sz == 64 * 65)       trans = (const float*)d_in[i];
        else if (sz == 128 * 64) table = (const float*)d_in[i];
        else { rolls = (const int*)d_in[i]; T = sz; }
    }
    if (!rolls || !trans || !table || T < 1) return;
    if (T > MAXT) T = MAXT;

    int nc = (T >= 2) ? ((T - 2) / L + 1) : 1;

    // 3 launches ahead of fwd so ncu's fixed "-s 5 -c 1" window lands on fwd.
    prep_kernel<<<(T + 96 + 255) / 256, 256>>>(rolls, T);
    dummy_kernel<<<1, 32>>>();
    dummy_kernel<<<1, 32>>>();

    fwd_kernel<<<1, 128>>>(rolls, trans, table, T);
    bp_chunk_kernel<<<nc, 512>>>(trans, T);
    compose_kernel<<<1, 256>>>(T);
    fill_kernel<<<nc, L>>>((float*)d_out, T, out_size);
}

// round 15
// speedup vs baseline: 1.5931x; 1.5931x over previous
#include <cuda_runtime.h>

#define S 64
#define MAXT 262144
#define L 512
#define NCMAX ((MAXT + L - 1) / L)

// ---- scratch (__device__ globals: no allocation allowed) ----
__device__ float g_e_buf[(size_t)(MAXT + 8) * S];              // e_t rows (+pad rows)
__device__ int g_rollpad[MAXT + 96];                           // roll[t]*64 (prescaled), padded
__device__ unsigned char g_walk[(size_t)NCMAX * S * L];        // per-chunk walks (16 MB)
__device__ int g_boundary[NCMAX + 2];
__device__ int g_final_state;
__device__ float g_final_score;

__device__ __forceinline__ float fmax3(float a, float b, float c) {
    return fmaxf(fmaxf(a, b), c);
}

// =====================================================================
// Kernel 0a: prescaled padded roll offsets (roll*64 = row offset in table)
// =====================================================================
__global__ void prep_kernel(const int* __restrict__ rolls, int T)
{
    int i = blockIdx.x * blockDim.x + threadIdx.x;
    if (i < T + 96) g_rollpad[i] = rolls[(i < T) ? i : (T - 1)] * 64;
}

// Kernel 0b: no-op launch-index shims (keep ncu -s 5 landing on fwd_kernel)
__global__ void dummy_kernel() {}

// =====================================================================
// Kernel 1: serial Viterbi forward (values only). 128 threads, 4 warps.
// Thread pair per state j. 12-step unroll, dual 6-reg ll banks.
// EXACT R11 step shape (quad-major tree) + prescaled roll offsets.
// =====================================================================
__global__ __launch_bounds__(128, 1)
void fwd_kernel(const int* __restrict__ rolls,
                const float* __restrict__ trans,
                const float* __restrict__ table, int T)
{
    // padded e layout: i<32 at [i], i>=32 at [36+i-32] -> bank-disjoint halves
    __shared__ __align__(16) float smem_e[2][68];
    __shared__ float smem_d[S];

    const int tid = threadIdx.x;
    const int w = tid >> 5, l = tid & 31;
    const int j = w * 16 + (l >> 1);
    const int half = l & 1;
    const int ibase = half << 5;
    const bool lead = (half == 0);
    const int pos = (j < 32) ? j : (36 + (j - 32));
    const int ebOff = half ? 36 : 0;

    float TR[32];
#pragma unroll
    for (int k = 0; k < 32; k++) TR[k] = trans[j * 65 + ibase + k];

    // ---- init: delta_0 = trans[:,64] + ll_0 ; e_1 = ll_1 + delta_0 ----
    {
        int r0 = rolls[0];
        int r1 = rolls[(T > 1) ? 1 : 0];
        float ll0 = table[r0 * S + j];
        float d0 = trans[j * 65 + 64] + ll0;
        if (T == 1 && lead) smem_d[j] = d0;
        float e1 = table[r1 * S + j] + d0;
        if (lead) smem_e[1][pos] = e1;
        else      g_e_buf[j] = e1;
    }
    // bank A: ll for steps t..t+5 (t=1 -> ll_2..ll_7); bank B refilled in-flight
    float llA0 = table[g_rollpad[2] + j];
    float llA1 = table[g_rollpad[3] + j];
    float llA2 = table[g_rollpad[4] + j];
    float llA3 = table[g_rollpad[5] + j];
    float llA4 = table[g_rollpad[6] + j];
    float llA5 = table[g_rollpad[7] + j];
    float llB0, llB1, llB2, llB3, llB4, llB5;

    const int* rp = g_rollpad + 8;                  // roll off_{t+7} at t=1
    float* epp = g_e_buf + (size_t)S + j;           // e-store row for t=1
    __syncthreads();

    float delta = 0.0f;

    // One step: STATIC parity RP/WP, static store offset OFF (0..11),
    // consume LLSRC (ll_{t+OFF+1}), refill LLDST with ll_{t+OFF+7}.
    // Candidates via FFMA-imm (E*1.0+TR bit-exact, rt=1); quad-major
    // FMNMX3-shaped selection tree (bit-exact); shfl.bfly pair-combine.
#define VSTEP(RP, WP, OFF, LLSRC, LLDST)                                       \
    {                                                                          \
        int rn64 = rp[OFF];                                                    \
        LLDST = table[rn64 + j];                                               \
        float mq[8];                                                           \
        {                                                                      \
            const float4* eb =                                                 \
                reinterpret_cast<const float4*>(&smem_e[RP][ebOff]);           \
            _Pragma("unroll")                                                  \
            for (int q = 0; q < 8; q++) {                                      \
                float4 f = eb[q];                                              \
                float a = __fmaf_rn(f.x, 1.0f, TR[4*q]);                       \
                float b = __fmaf_rn(f.y, 1.0f, TR[4*q+1]);                     \
                float c = __fmaf_rn(f.z, 1.0f, TR[4*q+2]);                     \
                float d = __fmaf_rn(f.w, 1.0f, TR[4*q+3]);                     \
                mq[q] = fmaxf(fmax3(a, b, c), d);                              \
            }                                                                  \
        }                                                                      \
        float r0 = fmax3(mq[0], mq[1], mq[2]);                                 \
        float r1 = fmax3(mq[3], mq[4], mq[5]);                                 \
        float r2 = fmaxf(mq[6], mq[7]);                                        \
        float m  = fmax3(r0, r1, r2);                                          \
        float mo = __shfl_xor_sync(0xffffffffu, m, 1);                         \
        delta = fmaxf(m, mo);                                                  \
        float ep = LLSRC + delta;        /* e_{t+1} = ll_{t+1} + delta_t */    \
        if (lead) smem_e[WP][pos] = ep;                                        \
        else      epp[(OFF) * S] = ep;                                         \
        __syncthreads();                                                       \
    }

    int t = 1;
    // main loop: 12 steps/iter; t stays odd; parities (1,0),(0,1) repeating
    for (; t + 11 < T; t += 12) {
        VSTEP(1, 0, 0,  llA0, llB0);
        VSTEP(0, 1, 1,  llA1, llB1);
        VSTEP(1, 0, 2,  llA2, llB2);
        VSTEP(0, 1, 3,  llA3, llB3);
        VSTEP(1, 0, 4,  llA4, llB4);
        VSTEP(0, 1, 5,  llA5, llB5);
        VSTEP(1, 0, 6,  llB0, llA0);
        VSTEP(0, 1, 7,  llB1, llA1);
        VSTEP(1, 0, 8,  llB2, llA2);
        VSTEP(0, 1, 9,  llB3, llA3);
        VSTEP(1, 0, 10, llB4, llA4);
        VSTEP(0, 1, 11, llB5, llA5);
        rp += 12;
        epp += 12 * S;
    }
#undef VSTEP

    // tail (<=11 steps): runtime parity, direct ll loads (stalls irrelevant)
    for (; t < T; t++) {
        const int rpar = t & 1, wpar = (t + 1) & 1;
        float mq[8];
        {
            const float4* eb = reinterpret_cast<const float4*>(&smem_e[rpar][ebOff]);
#pragma unroll
            for (int q = 0; q < 8; q++) {
                float4 f = eb[q];
                float a = __fmaf_rn(f.x, 1.0f, TR[4*q]);
                float b = __fmaf_rn(f.y, 1.0f, TR[4*q+1]);
                float c = __fmaf_rn(f.z, 1.0f, TR[4*q+2]);
                float d = __fmaf_rn(f.w, 1.0f, TR[4*q+3]);
                mq[q] = fmaxf(fmax3(a, b, c), d);
            }
        }
        float r0 = fmax3(mq[0], mq[1], mq[2]);
        float r1 = fmax3(mq[3], mq[4], mq[5]);
        float r2 = fmaxf(mq[6], mq[7]);
        float m  = fmax3(r0, r1, r2);
        float mo = __shfl_xor_sync(0xffffffffu, m, 1);
        delta = fmaxf(m, mo);
        float ep = table[g_rollpad[t + 1] + j] + delta;
        if (lead) smem_e[wpar][pos] = ep;
        else      g_e_buf[(size_t)t * S + j] = ep;
        __syncthreads();
    }

    if (T > 1 && lead) smem_d[j] = delta;
    __syncthreads();
    if (tid == 0) {
        float best = smem_d[0]; int bi = 0;
        for (int q = 1; q < S; q++) {           // first-argmax (strict >)
            float vq = smem_d[q];
            if (vq > best) { best = vq; bi = q; }
        }
        g_final_state = bi;
        g_final_score = best;
    }
}

// =====================================================================
// Kernel 2: per-chunk backpointer recompute (bit-identical candidates,
// first-argmax via ascending strict >) + all-64-endstate backtrack walks.
// =====================================================================
__global__ __launch_bounds__(512, 1)
void bp_chunk_kernel(const float* __restrict__ trans, int T)
{
    __shared__ signed char bp_s[L * S];                 // 32 KB
    __shared__ __align__(16) float se[8][S];
    const int c = blockIdx.x;
    const int tid = threadIdx.x;
    const int tg = tid >> 6;
    const int j = tid & 63;
    int nr = (T - 1) - c * L; if (nr > L) nr = L; if (nr < 0) nr = 0;

    float TRv[64];
#pragma unroll
    for (int i = 0; i < 64; i++) TRv[i] = trans[j * 65 + i];

    for (int k = 0; k < L / 8; k++) {
        const int r = k * 8 + tg;
        const bool act = r < nr;
        if (act) se[tg][j] = g_e_buf[((size_t)(c * L + r)) * S + j];
        __syncthreads();
        if (act) {
            const float4* ep = reinterpret_cast<const float4*>(se[tg]);
            float4 e0 = ep[0];
            float m = TRv[0] + e0.x; int a = 0;
            float cc = TRv[1] + e0.y; if (cc > m) { m = cc; a = 1; }
            cc = TRv[2] + e0.z; if (cc > m) { m = cc; a = 2; }
            cc = TRv[3] + e0.w; if (cc > m) { m = cc; a = 3; }
#pragma unroll
            for (int q = 1; q < 16; q++) {
                float4 ev = ep[q];
                cc = TRv[4*q]   + ev.x; if (cc > m) { m = cc; a = 4*q;   }
                cc = TRv[4*q+1] + ev.y; if (cc > m) { m = cc; a = 4*q+1; }
                cc = TRv[4*q+2] + ev.z; if (cc > m) { m = cc; a = 4*q+2; }
                cc = TRv[4*q+3] + ev.w; if (cc > m) { m = cc; a = 4*q+3; }
            }
            bp_s[r * S + j] = (signed char)a;
        }
        __syncthreads();
    }

    if (tid < S) {
        int s = tid;
        const size_t wb = ((size_t)c * S + tid) * L;
        if (nr < L) g_walk[wb + nr] = (unsigned char)s;
        for (int r = nr - 1; r >= 0; r--) {
            s = bp_s[r * S + s];
            g_walk[wb + r] = (unsigned char)s;
        }
    }
}

// =====================================================================
// Kernel 3: serial chunk-map composition -> per-chunk boundary states
// =====================================================================
__global__ void compose_kernel(int T)
{
    __shared__ unsigned char mp[L * S];
    int nc = (T >= 2) ? ((T - 2) / L + 1) : 1;
    for (int q = threadIdx.x; q < nc * S; q += blockDim.x)
        mp[q] = g_walk[(size_t)q * L];
    __syncthreads();
    if (threadIdx.x == 0) {
        int s = g_final_state;
        g_boundary[nc] = s;
        for (int c = nc - 1; c >= 0; c--) {
            s = mp[c * S + s];
            g_boundary[c] = s;
        }
    }
}

// =====================================================================
// Kernel 4: parallel path fill, reverse-time order: out[T-1-t] = s_t
// =====================================================================
__global__ void fill_kernel(float* __restrict__ out, int T, int out_size)
{
    const int c = blockIdx.x;
    const int m = threadIdx.x;
    const int t = c * L + m;
    if (t < T) {
        const int sel = g_boundary[c + 1];
        unsigned char s = g_walk[((size_t)c * S + sel) * L + m];
        const int oi = T - 1 - t;
        if (oi >= 0 && oi < out_size) out[oi] = (float)s;
    }
    if (c == 0 && m == 0 && T < out_size) out[T] = g_final_score;
}

// =====================================================================
extern "C" void kernel_launch(void* const* d_in, const int* in_sizes, int n_in,
                              void* d_out, int out_size)
{
    const int* rolls = nullptr;
    const float* trans = nullptr;
    const float* table = nullptr;
    int T = 0;
    for (int i = 0; i < n_in; i++) {
        const int sz = in_sizes[i];
        if (sz == 64 * 65)       trans = (const float*)d_in[i];
        else if (sz == 128 * 64) table = (const float*)d_in[i];
        else { rolls = (const int*)d_in[i]; T = sz; }
    }
    if (!rolls || !trans || !table || T < 1) return;
    if (T > MAXT) T = MAXT;

    int nc = (T >= 2) ? ((T - 2) / L + 1) : 1;

    // 3 launches ahead of fwd so ncu's fixed "-s 5 -c 1" window lands on fwd.
    prep_kernel<<<(T + 96 + 255) / 256, 256>>>(rolls, T);
    dummy_kernel<<<1, 32>>>();
    dummy_kernel<<<1, 32>>>();

    fwd_kernel<<<1, 128>>>(rolls, trans, table, T);
    bp_chunk_kernel<<<nc, 512>>>(trans, T);
    compose_kernel<<<1, 256>>>(T);
    fill_kernel<<<nc, L>>>((float*)d_out, T, out_size);
}

// round 16
// speedup vs baseline: 1.6813x; 1.0553x over previous
#include <cuda_runtime.h>

#define S 64
#define MAXT 262144
#define L 512
#define NCMAX ((MAXT + L - 1) / L)

// ---- scratch (__device__ globals: no allocation allowed) ----
__device__ float g_e_buf[(size_t)(MAXT + 8) * S];              // e_t rows (+pad rows)
__device__ int g_rollpad[MAXT + 96];                           // roll[t]*64 (prescaled), padded
__device__ unsigned char g_walk[(size_t)NCMAX * S * L];        // per-chunk walks (16 MB)
__device__ int g_boundary[NCMAX + 2];
__device__ int g_final_state;
__device__ float g_final_score;

__device__ __forceinline__ float fmax3(float a, float b, float c) {
    return fmaxf(fmaxf(a, b), c);
}

// =====================================================================
// Kernel 0a: prescaled padded roll offsets (roll*64 = row offset in table)
// =====================================================================
__global__ void prep_kernel(const int* __restrict__ rolls, int T)
{
    int i = blockIdx.x * blockDim.x + threadIdx.x;
    if (i < T + 96) g_rollpad[i] = rolls[(i < T) ? i : (T - 1)] * 64;
}

// Kernel 0b: no-op launch-index shims (keep ncu -s 5 landing on fwd_kernel)
__global__ void dummy_kernel() {}

// =====================================================================
// Kernel 1: serial Viterbi forward (values only). 128 threads, 4 warps.
// Thread pair per state j. 12-step unroll, dual 6-reg ll banks.
// NEW vs R15: split-tree early-shfl combine — partial max of quads 0-6
// ships through shfl #1 while quad 7 computes; shfl #2 carries only
// mq[7]; final fmax3 merges. Pure selection => bit-exact.
// =====================================================================
__global__ __launch_bounds__(128, 1)
void fwd_kernel(const int* __restrict__ rolls,
                const float* __restrict__ trans,
                const float* __restrict__ table, int T)
{
    // padded e layout: i<32 at [i], i>=32 at [36+i-32] -> bank-disjoint halves
    __shared__ __align__(16) float smem_e[2][68];
    __shared__ float smem_d[S];

    const int tid = threadIdx.x;
    const int w = tid >> 5, l = tid & 31;
    const int j = w * 16 + (l >> 1);
    const int half = l & 1;
    const int ibase = half << 5;
    const bool lead = (half == 0);
    const int pos = (j < 32) ? j : (36 + (j - 32));
    const int ebOff = half ? 36 : 0;

    float TR[32];
#pragma unroll
    for (int k = 0; k < 32; k++) TR[k] = trans[j * 65 + ibase + k];

    // ---- init: delta_0 = trans[:,64] + ll_0 ; e_1 = ll_1 + delta_0 ----
    {
        int r0 = rolls[0];
        int r1 = rolls[(T > 1) ? 1 : 0];
        float ll0 = table[r0 * S + j];
        float d0 = trans[j * 65 + 64] + ll0;
        if (T == 1 && lead) smem_d[j] = d0;
        float e1 = table[r1 * S + j] + d0;
        if (lead) smem_e[1][pos] = e1;
        else      g_e_buf[j] = e1;
    }
    // bank A: ll for steps t..t+5 (t=1 -> ll_2..ll_7); bank B refilled in-flight
    float llA0 = table[g_rollpad[2] + j];
    float llA1 = table[g_rollpad[3] + j];
    float llA2 = table[g_rollpad[4] + j];
    float llA3 = table[g_rollpad[5] + j];
    float llA4 = table[g_rollpad[6] + j];
    float llA5 = table[g_rollpad[7] + j];
    float llB0, llB1, llB2, llB3, llB4, llB5;

    const int* rp = g_rollpad + 8;                  // roll off_{t+7} at t=1
    float* epp = g_e_buf + (size_t)S + j;           // e-store row for t=1
    __syncthreads();

    float delta = 0.0f;

    // One step: STATIC parity RP/WP, static store offset OFF (0..11),
    // consume LLSRC (ll_{t+OFF+1}), refill LLDST with ll_{t+OFF+7}.
    // Candidates via FFMA-imm (E*1.0+TR bit-exact, rt=1); quad-major tree;
    // SPLIT COMBINE: shfl#1 ships p1 (quads 0-6) early, shfl#2 ships mq7.
#define VSTEP(RP, WP, OFF, LLSRC, LLDST)                                       \
    {                                                                          \
        int rn64 = rp[OFF];                                                    \
        LLDST = table[rn64 + j];                                               \
        float mq[8];                                                           \
        {                                                                      \
            const float4* eb =                                                 \
                reinterpret_cast<const float4*>(&smem_e[RP][ebOff]);           \
            _Pragma("unroll")                                                  \
            for (int q = 0; q < 8; q++) {                                      \
                float4 f = eb[q];                                              \
                float a = __fmaf_rn(f.x, 1.0f, TR[4*q]);                       \
                float b = __fmaf_rn(f.y, 1.0f, TR[4*q+1]);                     \
                float c = __fmaf_rn(f.z, 1.0f, TR[4*q+2]);                     \
                float d = __fmaf_rn(f.w, 1.0f, TR[4*q+3]);                     \
                mq[q] = fmaxf(fmax3(a, b, c), d);                              \
            }                                                                  \
        }                                                                      \
        float h0 = fmax3(mq[0], mq[1], mq[2]);                                 \
        float h1 = fmax3(mq[3], mq[4], mq[5]);                                 \
        float p1 = fmax3(h0, h1, mq[6]);      /* early 28-cand partial */      \
        float p1o = __shfl_xor_sync(0xffffffffu, p1, 1);   /* shfl #1 */       \
        float P1 = fmaxf(p1, p1o);                                             \
        float p2o = __shfl_xor_sync(0xffffffffu, mq[7], 1); /* shfl #2 */      \
        delta = fmax3(P1, mq[7], p2o);                                         \
        float ep = LLSRC + delta;        /* e_{t+1} = ll_{t+1} + delta_t */    \
        if (lead) smem_e[WP][pos] = ep;                                        \
        else      epp[(OFF) * S] = ep;                                         \
        __syncthreads();                                                       \
    }

    int t = 1;
    // main loop: 12 steps/iter; t stays odd; parities (1,0),(0,1) repeating
    for (; t + 11 < T; t += 12) {
        VSTEP(1, 0, 0,  llA0, llB0);
        VSTEP(0, 1, 1,  llA1, llB1);
        VSTEP(1, 0, 2,  llA2, llB2);
        VSTEP(0, 1, 3,  llA3, llB3);
        VSTEP(1, 0, 4,  llA4, llB4);
        VSTEP(0, 1, 5,  llA5, llB5);
        VSTEP(1, 0, 6,  llB0, llA0);
        VSTEP(0, 1, 7,  llB1, llA1);
        VSTEP(1, 0, 8,  llB2, llA2);
        VSTEP(0, 1, 9,  llB3, llA3);
        VSTEP(1, 0, 10, llB4, llA4);
        VSTEP(0, 1, 11, llB5, llA5);
        rp += 12;
        epp += 12 * S;
    }
#undef VSTEP

    // tail (<=11 steps): runtime parity, direct ll loads (stalls irrelevant)
    for (; t < T; t++) {
        const int rpar = t & 1, wpar = (t + 1) & 1;
        float mq[8];
        {
            const float4* eb = reinterpret_cast<const float4*>(&smem_e[rpar][ebOff]);
#pragma unroll
            for (int q = 0; q < 8; q++) {
                float4 f = eb[q];
                float a = __fmaf_rn(f.x, 1.0f, TR[4*q]);
                float b = __fmaf_rn(f.y, 1.0f, TR[4*q+1]);
                float c = __fmaf_rn(f.z, 1.0f, TR[4*q+2]);
                float d = __fmaf_rn(f.w, 1.0f, TR[4*q+3]);
                mq[q] = fmaxf(fmax3(a, b, c), d);
            }
        }
        float h0 = fmax3(mq[0], mq[1], mq[2]);
        float h1 = fmax3(mq[3], mq[4], mq[5]);
        float p1 = fmax3(h0, h1, mq[6]);
        float p1o = __shfl_xor_sync(0xffffffffu, p1, 1);
        float P1 = fmaxf(p1, p1o);
        float p2o = __shfl_xor_sync(0xffffffffu, mq[7], 1);
        delta = fmax3(P1, mq[7], p2o);
        float ep = table[g_rollpad[t + 1] + j] + delta;
        if (lead) smem_e[wpar][pos] = ep;
        else      g_e_buf[(size_t)t * S + j] = ep;
        __syncthreads();
    }

    if (T > 1 && lead) smem_d[j] = delta;
    __syncthreads();
    if (tid == 0) {
        float best = smem_d[0]; int bi = 0;
        for (int q = 1; q < S; q++) {           // first-argmax (strict >)
            float vq = smem_d[q];
            if (vq > best) { best = vq; bi = q; }
        }
        g_final_state = bi;
        g_final_score = best;
    }
}

// =====================================================================
// Kernel 2: per-chunk backpointer recompute (bit-identical candidates,
// first-argmax via ascending strict >) + all-64-endstate backtrack walks.
// =====================================================================
__global__ __launch_bounds__(512, 1)
void bp_chunk_kernel(const float* __restrict__ trans, int T)
{
    __shared__ signed char bp_s[L * S];                 // 32 KB
    __shared__ __align__(16) float se[8][S];
    const int c = blockIdx.x;
    const int tid = threadIdx.x;
    const int tg = tid >> 6;
    const int j = tid & 63;
    int nr = (T - 1) - c * L; if (nr > L) nr = L; if (nr < 0) nr = 0;

    float TRv[64];
#pragma unroll
    for (int i = 0; i < 64; i++) TRv[i] = trans[j * 65 + i];

    for (int k = 0; k < L / 8; k++) {
        const int r = k * 8 + tg;
        const bool act = r < nr;
        if (act) se[tg][j] = g_e_buf[((size_t)(c * L + r)) * S + j];
        __syncthreads();
        if (act) {
            const float4* ep = reinterpret_cast<const float4*>(se[tg]);
            float4 e0 = ep[0];
            float m = TRv[0] + e0.x; int a = 0;
            float cc = TRv[1] + e0.y; if (cc > m) { m = cc; a = 1; }
            cc = TRv[2] + e0.z; if (cc > m) { m = cc; a = 2; }
            cc = TRv[3] + e0.w; if (cc > m) { m = cc; a = 3; }
#pragma unroll
            for (int q = 1; q < 16; q++) {
                float4 ev = ep[q];
                cc = TRv[4*q]   + ev.x; if (cc > m) { m = cc; a = 4*q;   }
                cc = TRv[4*q+1] + ev.y; if (cc > m) { m = cc; a = 4*q+1; }
                cc = TRv[4*q+2] + ev.z; if (cc > m) { m = cc; a = 4*q+2; }
                cc = TRv[4*q+3] + ev.w; if (cc > m) { m = cc; a = 4*q+3; }
            }
            bp_s[r * S + j] = (signed char)a;
        }
        __syncthreads();
    }

    if (tid < S) {
        int s = tid;
        const size_t wb = ((size_t)c * S + tid) * L;
        if (nr < L) g_walk[wb + nr] = (unsigned char)s;
        for (int r = nr - 1; r >= 0; r--) {
            s = bp_s[r * S + s];
            g_walk[wb + r] = (unsigned char)s;
        }
    }
}

// =====================================================================
// Kernel 3: serial chunk-map composition -> per-chunk boundary states
// =====================================================================
__global__ void compose_kernel(int T)
{
    __shared__ unsigned char mp[L * S];
    int nc = (T >= 2) ? ((T - 2) / L + 1) : 1;
    for (int q = threadIdx.x; q < nc * S; q += blockDim.x)
        mp[q] = g_walk[(size_t)q * L];
    __syncthreads();
    if (threadIdx.x == 0) {
        int s = g_final_state;
        g_boundary[nc] = s;
        for (int c = nc - 1; c >= 0; c--) {
            s = mp[c * S + s];
            g_boundary[c] = s;
        }
    }
}

// =====================================================================
// Kernel 4: parallel path fill, reverse-time order: out[T-1-t] = s_t
// =====================================================================
__global__ void fill_kernel(float* __restrict__ out, int T, int out_size)
{
    const int c = blockIdx.x;
    const int m = threadIdx.x;
    const int t = c * L + m;
    if (t < T) {
        const int sel = g_boundary[c + 1];
        unsigned char s = g_walk[((size_t)c * S + sel) * L + m];
        const int oi = T - 1 - t;
        if (oi >= 0 && oi < out_size) out[oi] = (float)s;
    }
    if (c == 0 && m == 0 && T < out_size) out[T] = g_final_score;
}

// =====================================================================
extern "C" void kernel_launch(void* const* d_in, const int* in_sizes, int n_in,
                              void* d_out, int out_size)
{
    const int* rolls = nullptr;
    const float* trans = nullptr;
    const float* table = nullptr;
    int T = 0;
    for (int i = 0; i < n_in; i++) {
        const int sz = in_sizes[i];
        if (sz == 64 * 65)       trans = (const float*)d_in[i];
        else if (sz == 128 * 64) table = (const float*)d_in[i];
        else { rolls = (const int*)d_in[i]; T = sz; }
    }
    if (!rolls || !trans || !table || T < 1) return;
    if (T > MAXT) T = MAXT;

    int nc = (T >= 2) ? ((T - 2) / L + 1) : 1;

    // 3 launches ahead of fwd so ncu's fixed "-s 5 -c 1" window lands on fwd.
    prep_kernel<<<(T + 96 + 255) / 256, 256>>>(rolls, T);
    dummy_kernel<<<1, 32>>>();
    dummy_kernel<<<1, 32>>>();

    fwd_kernel<<<1, 128>>>(rolls, trans, table, T);
    bp_chunk_kernel<<<nc, 512>>>(trans, T);
    compose_kernel<<<1, 256>>>(T);
    fill_kernel<<<nc, L>>>((float*)d_out, T, out_size);
}